// round 10
// baseline (speedup 1.0000x reference)
#include <cuda_runtime.h>

#define NB_VARS 2000000
#define M0 4000000
#define M1 1000000
#define M2 500000
#define M3 125000
#define E1 8000000
#define E3 1000000

// Scratch (allocation-free rule: __device__ globals; zero-initialized at load)
__device__ float g_y0[M0];
__device__ float g_y1[M1];
__device__ float g_y2[M2];
__device__ int g_start1[M1];
__device__ int g_end1[M1];    // 0 = empty segment (never written; unique writer per location otherwise)
__device__ int g_start3[M3];
__device__ int g_end3[M3];

// Fused input encoding: x = [0, 1, p0, 1-p0, p1, 1-p1, ...]
__device__ __forceinline__ float leaf_val(const float* __restrict__ xp, int idx) {
    if (idx >= 2) {
        float p = __ldg(xp + ((idx - 2) >> 1));
        return (idx & 1) ? (1.0f - p) : p;
    }
    return (float)idx;  // 0 -> 0.0, 1 -> 1.0
}

// Segment boundary pass: ix_out sorted; first/last occurrence of each segment id
// has a unique writer -> deterministic scatter. n must be divisible by 4.
__global__ void __launch_bounds__(256) bounds_kernel(const int* __restrict__ ixo,
                                                     int* __restrict__ start,
                                                     int* __restrict__ end, int n) {
    int t = blockIdx.x * blockDim.x + threadIdx.x;
    int e = 4 * t;
    if (e >= n) return;
    int4 s = __ldg((const int4*)ixo + t);
    if (e == 0) start[s.x] = 0;
    else { int prev = __ldg(ixo + e - 1); if (s.x != prev) start[s.x] = e; }
    if (s.y != s.x) { end[s.x] = e + 1; start[s.y] = e + 1; }
    if (s.z != s.y) { end[s.y] = e + 2; start[s.z] = e + 2; }
    if (s.w != s.z) { end[s.z] = e + 3; start[s.w] = e + 3; }
    if (e + 4 >= n) end[s.w] = n;
    else { int next = __ldg(ixo + e + 4); if (next != s.w) end[s.w] = e + 4; }
}

// Layer 0: 2 products per thread (4 gathers), float2 store. 2M threads.
__global__ void __launch_bounds__(256) layer0_kernel(const float* __restrict__ xp,
                                                     const int4* __restrict__ ix) {
    int t = blockIdx.x * blockDim.x + threadIdx.x;     // [0, M0/2)
    if (t >= M0 / 2) return;
    int4 v = __ldg(ix + t);
    float2 r;
    r.x = leaf_val(xp, v.x) * leaf_val(xp, v.y);
    r.y = leaf_val(xp, v.z) * leaf_val(xp, v.w);
    ((float2*)g_y0)[t] = r;
}

// Output-major segment sum: one thread per output segment; edges [lo,hi) are
// contiguous (sorted ix_out). No atomics, no zero-init, plain coalesced store.
// Empty segments (end==0 -> hi<=lo path writes 0). 4-unrolled for gather MLP.
__device__ __forceinline__ void segsum_om(const int* __restrict__ ixi,
                                          const int* __restrict__ start,
                                          const int* __restrict__ end,
                                          const float* __restrict__ src,
                                          float* __restrict__ dst, int m) {
    int t = blockIdx.x * blockDim.x + threadIdx.x;
    if (t >= m) return;
    int hi = __ldg(end + t);
    int lo = (hi > 0) ? __ldg(start + t) : 0;
    float acc = 0.0f;
    int k = lo;
    for (; k + 4 <= hi; k += 4) {
        int i0 = __ldg(ixi + k);
        int i1 = __ldg(ixi + k + 1);
        int i2 = __ldg(ixi + k + 2);
        int i3 = __ldg(ixi + k + 3);
        acc += __ldg(src + i0) + __ldg(src + i1) + __ldg(src + i2) + __ldg(src + i3);
    }
    for (; k < hi; k++) acc += __ldg(src + __ldg(ixi + k));
    dst[t] = acc;
}

__global__ void __launch_bounds__(256) segsum1_kernel(const int* __restrict__ ix_in) {
    segsum_om(ix_in, g_start1, g_end1, g_y0, g_y1, M1);
}

// Layer 2: 2 products per thread over g_y1 -> g_y2. 250K threads.
__global__ void __launch_bounds__(256) layer2_kernel(const int4* __restrict__ ix) {
    int t = blockIdx.x * blockDim.x + threadIdx.x;     // [0, M2/2)
    if (t >= M2 / 2) return;
    int4 v = __ldg(ix + t);
    float2 r;
    r.x = __ldg(g_y1 + v.x) * __ldg(g_y1 + v.y);
    r.y = __ldg(g_y1 + v.z) * __ldg(g_y1 + v.w);
    ((float2*)g_y2)[t] = r;
}

__global__ void __launch_bounds__(256) segsum3_kernel(const int* __restrict__ ix_in,
                                                      float* __restrict__ out) {
    segsum_om(ix_in, g_start3, g_end3, g_y2, out, M3);
}

extern "C" void kernel_launch(void* const* d_in, const int* in_sizes, int n_in,
                              void* d_out, int out_size) {
    const float* x_pos   = (const float*)d_in[0];
    const int*   ix_in0  = (const int*)d_in[1];
    const int*   ix_in1  = (const int*)d_in[2];
    const int*   ix_out1 = (const int*)d_in[3];
    const int*   ix_in2  = (const int*)d_in[4];
    const int*   ix_in3  = (const int*)d_in[5];
    const int*   ix_out3 = (const int*)d_in[6];
    float* out = (float*)d_out;

    int* start1; int* end1; int* start3; int* end3;
    cudaGetSymbolAddress((void**)&start1, g_start1);
    cudaGetSymbolAddress((void**)&end1,   g_end1);
    cudaGetSymbolAddress((void**)&start3, g_start3);
    cudaGetSymbolAddress((void**)&end3,   g_end3);

    const int B = 256;
    bounds_kernel <<<(E1 / 4 + B - 1) / B, B>>>(ix_out1, start1, end1, E1);
    bounds_kernel <<<(E3 / 4 + B - 1) / B, B>>>(ix_out3, start3, end3, E3);
    layer0_kernel <<<(M0 / 2 + B - 1) / B, B>>>(x_pos, (const int4*)ix_in0);
    segsum1_kernel<<<(M1 + B - 1) / B, B>>>(ix_in1);
    layer2_kernel <<<(M2 / 2 + B - 1) / B, B>>>((const int4*)ix_in2);
    segsum3_kernel<<<(M3 + B - 1) / B, B>>>(ix_in3, out);
}

// round 11
// speedup vs baseline: 1.1622x; 1.1622x over previous
#include <cuda_runtime.h>

#define NB_VARS 2000000
#define M0 4000000
#define M1 1000000
#define M2 500000
#define M3 125000
#define E1 8000000
#define E3 1000000

// Scratch (allocation-free rule: __device__ globals)
__device__ float g_y0[M0];
__device__ float g_y1[M1];
__device__ float g_y2[M2];

// Fused input encoding: x = [0, 1, p0, 1-p0, p1, 1-p1, ...]
__device__ __forceinline__ float leaf_val(const float* __restrict__ xp, int idx) {
    if (idx >= 2) {
        float p = __ldg(xp + ((idx - 2) >> 1));
        return (idx & 1) ? (1.0f - p) : p;
    }
    return (float)idx;  // 0 -> 0.0, 1 -> 1.0
}

// Layer 0: 2 products per thread (4 gathers), float2 store. 2M threads.
// Also zeroes g_y1 and d_out (stream order guarantees completion before consumers).
__global__ void __launch_bounds__(256) layer0_kernel(const float* __restrict__ xp,
                                                     const int4* __restrict__ ix,
                                                     float* __restrict__ out_zero) {
    int t = blockIdx.x * blockDim.x + threadIdx.x;     // [0, M0/2)
    if (t < M1 / 4) ((float4*)g_y1)[t] = make_float4(0.f, 0.f, 0.f, 0.f);
    if (t < M3 / 4) ((float4*)out_zero)[t] = make_float4(0.f, 0.f, 0.f, 0.f);
    if (t >= M0 / 2) return;
    int4 v = __ldg(ix + t);
    float2 r;
    r.x = leaf_val(xp, v.x) * leaf_val(xp, v.y);
    r.y = leaf_val(xp, v.z) * leaf_val(xp, v.w);
    ((float2*)g_y0)[t] = r;
}

// Segsum layer 1: 4 edges/thread (2M threads), scan-free local run-merge + REDG.
// Runs spanning thread boundaries contribute via multiple atomics — still correct.
__global__ void __launch_bounds__(256) segsum1_kernel(const int4* __restrict__ ix_in,
                                                      const int4* __restrict__ ix_out) {
    int t = blockIdx.x * blockDim.x + threadIdx.x;     // [0, E1/4)
    if (t >= E1 / 4) return;
    int4 s = __ldg(ix_out + t);
    int4 g = __ldg(ix_in + t);
    // 4 independent gathers in flight
    float v0 = __ldg(g_y0 + g.x);
    float v1 = __ldg(g_y0 + g.y);
    float v2 = __ldg(g_y0 + g.z);
    float v3 = __ldg(g_y0 + g.w);
    float acc = v0;
    int cur = s.x;
    if (s.y == cur) acc += v1; else { atomicAdd(g_y1 + cur, acc); cur = s.y; acc = v1; }
    if (s.z == cur) acc += v2; else { atomicAdd(g_y1 + cur, acc); cur = s.z; acc = v2; }
    if (s.w == cur) acc += v3; else { atomicAdd(g_y1 + cur, acc); cur = s.w; acc = v3; }
    atomicAdd(g_y1 + cur, acc);
}

// Layer 2: 1 product per thread (max concurrency: 500K threads).
__global__ void __launch_bounds__(256) layer2_kernel(const int2* __restrict__ ix) {
    int t = blockIdx.x * blockDim.x + threadIdx.x;     // [0, M2)
    if (t >= M2) return;
    int2 v = __ldg(ix + t);
    g_y2[t] = __ldg(g_y1 + v.x) * __ldg(g_y1 + v.y);
}

// Segsum layer 3: 1 edge/thread (1M threads), one REDG per edge.
// Spread-address REDG throughput absorbs the 1M lanes; max latency hiding.
__global__ void __launch_bounds__(256) segsum3_kernel(const int* __restrict__ ix_in,
                                                      const int* __restrict__ ix_out,
                                                      float* __restrict__ out) {
    int t = blockIdx.x * blockDim.x + threadIdx.x;     // [0, E3)
    if (t >= E3) return;
    int s = __ldg(ix_out + t);
    float v = __ldg(g_y2 + __ldg(ix_in + t));
    atomicAdd(out + s, v);
}

extern "C" void kernel_launch(void* const* d_in, const int* in_sizes, int n_in,
                              void* d_out, int out_size) {
    const float* x_pos   = (const float*)d_in[0];
    const int*   ix_in0  = (const int*)d_in[1];
    const int*   ix_in1  = (const int*)d_in[2];
    const int*   ix_out1 = (const int*)d_in[3];
    const int*   ix_in2  = (const int*)d_in[4];
    const int*   ix_in3  = (const int*)d_in[5];
    const int*   ix_out3 = (const int*)d_in[6];
    float* out = (float*)d_out;

    const int B = 256;
    layer0_kernel <<<(M0 / 2 + B - 1) / B, B>>>(x_pos, (const int4*)ix_in0, out);
    segsum1_kernel<<<(E1 / 4 + B - 1) / B, B>>>((const int4*)ix_in1, (const int4*)ix_out1);
    layer2_kernel <<<(M2 + B - 1) / B, B>>>((const int2*)ix_in2);
    segsum3_kernel<<<(E3 + B - 1) / B, B>>>(ix_in3, ix_out3, out);
}

// round 12
// speedup vs baseline: 1.1939x; 1.0273x over previous
#include <cuda_runtime.h>

#define NB_VARS 2000000
#define M0 4000000
#define M1 1000000
#define M2 500000
#define M3 125000
#define E1 8000000
#define E3 1000000

#define TAIL_BLOCKS (148 * 8)   // single co-scheduled wave on 148 SMs @ 256 thr, no smem, low regs

// Scratch (allocation-free rule: __device__ globals)
__device__ float g_y0[M0];
__device__ float g_y1[M1];
__device__ float g_y2[M2];

// Fused input encoding: x = [0, 1, p0, 1-p0, p1, 1-p1, ...]
__device__ __forceinline__ float leaf_val(const float* __restrict__ xp, int idx) {
    if (idx >= 2) {
        float p = __ldg(xp + ((idx - 2) >> 1));
        return (idx & 1) ? (1.0f - p) : p;
    }
    return (float)idx;  // 0 -> 0.0, 1 -> 1.0
}

// Layer 0: 2 products per thread (4 gathers), float2 store. 2M threads.
// Also zeroes g_y1 and d_out (stream order guarantees completion before consumers).
__global__ void __launch_bounds__(256) layer0_kernel(const float* __restrict__ xp,
                                                     const int4* __restrict__ ix,
                                                     float* __restrict__ out_zero) {
    int t = blockIdx.x * blockDim.x + threadIdx.x;     // [0, M0/2)
    if (t < M1 / 4) ((float4*)g_y1)[t] = make_float4(0.f, 0.f, 0.f, 0.f);
    if (t < M3 / 4) ((float4*)out_zero)[t] = make_float4(0.f, 0.f, 0.f, 0.f);
    if (t >= M0 / 2) return;
    int4 v = __ldg(ix + t);
    float2 r;
    r.x = leaf_val(xp, v.x) * leaf_val(xp, v.y);
    r.y = leaf_val(xp, v.z) * leaf_val(xp, v.w);
    ((float2*)g_y0)[t] = r;
}

// Segsum layer 1: 4 edges/thread (2M threads), scan-free local run-merge + REDG.
// Runs spanning thread boundaries contribute via multiple atomics — still correct.
__global__ void __launch_bounds__(256) segsum1_kernel(const int4* __restrict__ ix_in,
                                                      const int4* __restrict__ ix_out) {
    int t = blockIdx.x * blockDim.x + threadIdx.x;     // [0, E1/4)
    if (t >= E1 / 4) return;
    int4 s = __ldg(ix_out + t);
    int4 g = __ldg(ix_in + t);
    // 4 independent gathers in flight
    float v0 = __ldg(g_y0 + g.x);
    float v1 = __ldg(g_y0 + g.y);
    float v2 = __ldg(g_y0 + g.z);
    float v3 = __ldg(g_y0 + g.w);
    float acc = v0;
    int cur = s.x;
    if (s.y == cur) acc += v1; else { atomicAdd(g_y1 + cur, acc); cur = s.y; acc = v1; }
    if (s.z == cur) acc += v2; else { atomicAdd(g_y1 + cur, acc); cur = s.z; acc = v2; }
    if (s.w == cur) acc += v3; else { atomicAdd(g_y1 + cur, acc); cur = s.w; acc = v3; }
    atomicAdd(g_y1 + cur, acc);
}

// Layer 2: single-wave grid-stride, 2 products per iteration (int4 index load).
__global__ void __launch_bounds__(256) layer2_kernel(const int4* __restrict__ ix) {
    int stride = gridDim.x * blockDim.x;
    for (int t = blockIdx.x * blockDim.x + threadIdx.x; t < M2 / 2; t += stride) {
        int4 v = __ldg(ix + t);
        float2 r;
        r.x = __ldg(g_y1 + v.x) * __ldg(g_y1 + v.y);
        r.y = __ldg(g_y1 + v.z) * __ldg(g_y1 + v.w);
        ((float2*)g_y2)[t] = r;
    }
}

// Segsum layer 3: single-wave grid-stride, 2 edges per iteration, pair merge + REDG.
__global__ void __launch_bounds__(256) segsum3_kernel(const int2* __restrict__ ix_in,
                                                      const int2* __restrict__ ix_out,
                                                      float* __restrict__ out) {
    int stride = gridDim.x * blockDim.x;
    for (int t = blockIdx.x * blockDim.x + threadIdx.x; t < E3 / 2; t += stride) {
        int2 s = __ldg(ix_out + t);
        int2 g = __ldg(ix_in + t);
        float v0 = __ldg(g_y2 + g.x);
        float v1 = __ldg(g_y2 + g.y);
        if (s.x == s.y) {
            atomicAdd(out + s.x, v0 + v1);
        } else {
            atomicAdd(out + s.x, v0);
            atomicAdd(out + s.y, v1);
        }
    }
}

extern "C" void kernel_launch(void* const* d_in, const int* in_sizes, int n_in,
                              void* d_out, int out_size) {
    const float* x_pos   = (const float*)d_in[0];
    const int*   ix_in0  = (const int*)d_in[1];
    const int*   ix_in1  = (const int*)d_in[2];
    const int*   ix_out1 = (const int*)d_in[3];
    const int*   ix_in2  = (const int*)d_in[4];
    const int*   ix_in3  = (const int*)d_in[5];
    const int*   ix_out3 = (const int*)d_in[6];
    float* out = (float*)d_out;

    const int B = 256;
    layer0_kernel <<<(M0 / 2 + B - 1) / B, B>>>(x_pos, (const int4*)ix_in0, out);
    segsum1_kernel<<<(E1 / 4 + B - 1) / B, B>>>((const int4*)ix_in1, (const int4*)ix_out1);
    layer2_kernel <<<TAIL_BLOCKS, B>>>((const int4*)ix_in2);
    segsum3_kernel<<<TAIL_BLOCKS, B>>>((const int2*)ix_in3, (const int2*)ix_out3, out);
}

// round 13
// speedup vs baseline: 1.2241x; 1.0252x over previous
#include <cuda_runtime.h>

#define NB_VARS 2000000
#define M0 4000000
#define M1 1000000
#define M2 500000
#define M3 125000
#define E1 8000000
#define E3 1000000

// Scratch (allocation-free rule: __device__ globals)
__device__ float g_y0[M0];
__device__ float g_y1[M1];
__device__ float g_y2[M2];

// Fused input encoding: x = [0, 1, p0, 1-p0, p1, 1-p1, ...]
__device__ __forceinline__ float leaf_val(const float* __restrict__ xp, int idx) {
    if (idx >= 2) {
        float p = __ldg(xp + ((idx - 2) >> 1));
        return (idx & 1) ? (1.0f - p) : p;
    }
    return (float)idx;  // 0 -> 0.0, 1 -> 1.0
}

// Layer 0: 2 products per thread (4 gathers), float2 store. 2M threads.
// Also zeroes g_y1 and d_out (PDL chain guarantees completion before consumers).
__global__ void __launch_bounds__(256) layer0_kernel(const float* __restrict__ xp,
                                                     const int4* __restrict__ ix,
                                                     float* __restrict__ out_zero) {
    int t = blockIdx.x * blockDim.x + threadIdx.x;     // [0, M0/2)
    if (t < M1 / 4) ((float4*)g_y1)[t] = make_float4(0.f, 0.f, 0.f, 0.f);
    if (t < M3 / 4) ((float4*)out_zero)[t] = make_float4(0.f, 0.f, 0.f, 0.f);
    if (t >= M0 / 2) return;
    int4 v = __ldg(ix + t);
    float2 r;
    r.x = leaf_val(xp, v.x) * leaf_val(xp, v.y);
    r.y = leaf_val(xp, v.z) * leaf_val(xp, v.w);
    ((float2*)g_y0)[t] = r;
}

// Segsum layer 1: 4 edges/thread (2M threads), scan-free local run-merge + REDG.
// PDL: stream index loads issued BEFORE the grid-dependency sync (fresh inputs,
// independent of layer0), overlapping layer0's drain tail.
__global__ void __launch_bounds__(256) segsum1_kernel(const int4* __restrict__ ix_in,
                                                      const int4* __restrict__ ix_out) {
    int t = blockIdx.x * blockDim.x + threadIdx.x;     // [0, E1/4)
    if (t >= E1 / 4) {
        cudaGridDependencySynchronize();
        return;
    }
    int4 s = __ldg(ix_out + t);
    int4 g = __ldg(ix_in + t);
    cudaGridDependencySynchronize();        // wait for layer0 (g_y0, zeroed g_y1)
    cudaTriggerProgrammaticLaunchCompletion();
    // 4 independent gathers in flight
    float v0 = __ldg(g_y0 + g.x);
    float v1 = __ldg(g_y0 + g.y);
    float v2 = __ldg(g_y0 + g.z);
    float v3 = __ldg(g_y0 + g.w);
    float acc = v0;
    int cur = s.x;
    if (s.y == cur) acc += v1; else { atomicAdd(g_y1 + cur, acc); cur = s.y; acc = v1; }
    if (s.z == cur) acc += v2; else { atomicAdd(g_y1 + cur, acc); cur = s.z; acc = v2; }
    if (s.w == cur) acc += v3; else { atomicAdd(g_y1 + cur, acc); cur = s.w; acc = v3; }
    atomicAdd(g_y1 + cur, acc);
}

// Layer 2: 2 products per thread over g_y1 -> g_y2. 250K threads. PDL as above.
__global__ void __launch_bounds__(256) layer2_kernel(const int4* __restrict__ ix) {
    int t = blockIdx.x * blockDim.x + threadIdx.x;     // [0, M2/2)
    if (t >= M2 / 2) {
        cudaGridDependencySynchronize();
        return;
    }
    int4 v = __ldg(ix + t);
    cudaGridDependencySynchronize();        // wait for segsum1 (g_y1 final)
    cudaTriggerProgrammaticLaunchCompletion();
    float2 r;
    r.x = __ldg(g_y1 + v.x) * __ldg(g_y1 + v.y);
    r.y = __ldg(g_y1 + v.z) * __ldg(g_y1 + v.w);
    ((float2*)g_y2)[t] = r;
}

// Segsum layer 3: 2 edges/thread (500K threads), pair merge + REDG. PDL as above.
__global__ void __launch_bounds__(256) segsum3_kernel(const int2* __restrict__ ix_in,
                                                      const int2* __restrict__ ix_out,
                                                      float* __restrict__ out) {
    int t = blockIdx.x * blockDim.x + threadIdx.x;     // [0, E3/2)
    if (t >= E3 / 2) {
        cudaGridDependencySynchronize();
        return;
    }
    int2 s = __ldg(ix_out + t);
    int2 g = __ldg(ix_in + t);
    cudaGridDependencySynchronize();        // wait for layer2 (g_y2; out zeroed transitively)
    float v0 = __ldg(g_y2 + g.x);
    float v1 = __ldg(g_y2 + g.y);
    if (s.x == s.y) {
        atomicAdd(out + s.x, v0 + v1);
    } else {
        atomicAdd(out + s.x, v0);
        atomicAdd(out + s.y, v1);
    }
}

template <typename... Args>
static void launch_pdl(void (*kern)(Args...), int grid, int block, Args... args) {
    cudaLaunchConfig_t cfg = {};
    cfg.gridDim = dim3(grid, 1, 1);
    cfg.blockDim = dim3(block, 1, 1);
    cudaLaunchAttribute attr[1];
    attr[0].id = cudaLaunchAttributeProgrammaticStreamSerialization;
    attr[0].val.programmaticStreamSerializationAllowed = 1;
    cfg.attrs = attr;
    cfg.numAttrs = 1;
    cfg.stream = 0;
    cudaLaunchKernelEx(&cfg, kern, args...);
}

extern "C" void kernel_launch(void* const* d_in, const int* in_sizes, int n_in,
                              void* d_out, int out_size) {
    const float* x_pos   = (const float*)d_in[0];
    const int*   ix_in0  = (const int*)d_in[1];
    const int*   ix_in1  = (const int*)d_in[2];
    const int*   ix_out1 = (const int*)d_in[3];
    const int*   ix_in2  = (const int*)d_in[4];
    const int*   ix_in3  = (const int*)d_in[5];
    const int*   ix_out3 = (const int*)d_in[6];
    float* out = (float*)d_out;

    const int B = 256;
    layer0_kernel<<<(M0 / 2 + B - 1) / B, B>>>(x_pos, (const int4*)ix_in0, out);
    launch_pdl(segsum1_kernel, (E1 / 4 + B - 1) / B, B,
               (const int4*)ix_in1, (const int4*)ix_out1);
    launch_pdl(layer2_kernel, (M2 / 2 + B - 1) / B, B, (const int4*)ix_in2);
    launch_pdl(segsum3_kernel, (E3 / 2 + B - 1) / B, B,
               (const int2*)ix_in3, (const int2*)ix_out3, out);
}